// round 2
// baseline (speedup 1.0000x reference)
#include <cuda_runtime.h>
#include <cuda_fp16.h>

#define NN 100000
#define EE 1600000
#define CC 8
#define HH 64
#define BB 16
#define NFEAT 140
#define CFEAT 18
#define OPED 64
#define ALPHAC 0.2f
#define ROWS (CC*NN)
#define GRP 8

typedef unsigned long long ull;

// ---------------- device scratch ----------------
__device__ float  g_x  [(size_t)ROWS*HH];   // node states (fp32) [c][n][h]
__device__ __half g_xdh[(size_t)ROWS*HH];   // x @ Wd, fp16 (SpMM gather operand)
__device__ float  g_y  [(size_t)ROWS*HH];   // SpMM output
__device__ float  g_xp [(size_t)ROWS*HH];   // layer-0 x @ Wp + bp
__device__ int    g_rowptr[NN+1];
__device__ int    g_wptr[NN];
__device__ int    g_col[2*EE];
__device__ float  g_pooled[BB*CC*HH];

__device__ __forceinline__ float lrelu(float v){ return v > 0.f ? v : ALPHAC*v; }

__device__ __forceinline__ float warp_sum(float v){
  v += __shfl_xor_sync(0xffffffffu, v, 16);
  v += __shfl_xor_sync(0xffffffffu, v, 8);
  v += __shfl_xor_sync(0xffffffffu, v, 4);
  v += __shfl_xor_sync(0xffffffffu, v, 2);
  v += __shfl_xor_sync(0xffffffffu, v, 1);
  return v;
}

// ---- packed f32x2 helpers ----
__device__ __forceinline__ ull f2_pack(float a, float b){
  ull r; asm("mov.b64 %0, {%1,%2};" : "=l"(r) : "f"(a), "f"(b)); return r;
}
__device__ __forceinline__ float2 f2_unpack(ull v){
  float2 r; asm("mov.b64 {%0,%1}, %2;" : "=f"(r.x), "=f"(r.y) : "l"(v)); return r;
}
__device__ __forceinline__ void fma2(ull &acc, ull a, ull b){
  asm("fma.rn.f32x2 %0, %1, %2, %0;" : "+l"(acc) : "l"(a), "l"(b));
}

// ---------------- CSR build (A + A^T) ----------------
__global__ void k_zero_counts() {
  int i = blockIdx.x*blockDim.x + threadIdx.x;
  if (i < NN) g_wptr[i] = 0;
}

__global__ void k_count(const int* __restrict__ src, const int* __restrict__ dst) {
  int e4 = blockIdx.x*blockDim.x + threadIdx.x;
  if (e4 < EE/4) {
    int4 s = __ldg((const int4*)src + e4);
    int4 d = __ldg((const int4*)dst + e4);
    atomicAdd(&g_wptr[d.x], 1); atomicAdd(&g_wptr[s.x], 1);
    atomicAdd(&g_wptr[d.y], 1); atomicAdd(&g_wptr[s.y], 1);
    atomicAdd(&g_wptr[d.z], 1); atomicAdd(&g_wptr[s.z], 1);
    atomicAdd(&g_wptr[d.w], 1); atomicAdd(&g_wptr[s.w], 1);
  }
}

__global__ void k_scan() {
  __shared__ int ss[1024];
  int t = threadIdx.x;
  const int CH = (NN + 1023) / 1024;
  int lo = t*CH;
  int hi = lo + CH; if (hi > NN) hi = NN;
  int s = 0;
  for (int i = lo; i < hi; i++) s += g_wptr[i];
  ss[t] = s;
  __syncthreads();
  for (int off = 1; off < 1024; off <<= 1) {
    int v = (t >= off) ? ss[t-off] : 0;
    __syncthreads();
    ss[t] += v;
    __syncthreads();
  }
  int run = (t == 0) ? 0 : ss[t-1];
  for (int i = lo; i < hi; i++) {
    int cv = g_wptr[i];
    g_rowptr[i] = run;
    g_wptr[i]   = run;
    run += cv;
  }
  if (t == 1023) g_rowptr[NN] = ss[1023];
}

__global__ void k_fill(const int* __restrict__ src, const int* __restrict__ dst) {
  int e = blockIdx.x*blockDim.x + threadIdx.x;
  if (e < EE) {
    int s = src[e], d = dst[e];
    int p = atomicAdd(&g_wptr[d], 1);  g_col[p] = s;
    int q = atomicAdd(&g_wptr[s], 1);  g_col[q] = d;
  }
}

// ---------------- layer 0: fused feature join + both projections ----------------
// warp-per-node, lane owns h = {2l, 2l+1}
__global__ void k_layer0(const float* __restrict__ node_feats,
                         const float* __restrict__ config_feats,
                         const int*   __restrict__ op_ids,
                         const float* __restrict__ op_emb,
                         const float* __restrict__ Wd,
                         const float* __restrict__ Wp,
                         const float* __restrict__ bp) {
  __shared__ float sBase[8*204];
  __shared__ float sCf[8*CC*CFEAT];
  int tid = threadIdx.x;
  int w = tid >> 5, l = tid & 31;
  float* myBase = sBase + w*204;
  float* myCf   = sCf + w*CC*CFEAT;
  int gw = (blockIdx.x*blockDim.x + tid) >> 5;
  int nw = (gridDim.x*blockDim.x) >> 5;
  const float2* Wd2 = (const float2*)Wd;
  const float2* Wp2 = (const float2*)Wp;
  float2 bpv = __ldg((const float2*)bp + l);

  for (int n = gw; n < NN; n += nw) {
    int oid = __ldg(op_ids + n);
    #pragma unroll
    for (int d = l; d < 204; d += 32)
      myBase[d] = (d < OPED) ? __ldg(op_emb + oid*OPED + d)
                             : __ldg(node_feats + (size_t)n*NFEAT + (d - OPED));
    #pragma unroll
    for (int j = l; j < CC*CFEAT; j += 32)
      myCf[j] = __ldg(config_feats + (size_t)n*CC*CFEAT + j);
    __syncwarp();

    float2 accD = make_float2(0.f, 0.f);
    float2 accP = make_float2(0.f, 0.f);
    #pragma unroll 4
    for (int d = 0; d < 204; d++) {
      float b = myBase[d];
      float2 wd = __ldg(Wd2 + d*32 + l);
      float2 wp = __ldg(Wp2 + d*32 + l);
      accD.x += b*wd.x; accD.y += b*wd.y;
      accP.x += b*wp.x; accP.y += b*wp.y;
    }
    // per-config accumulators (j outer so weights load once)
    float2 aD[CC], aP[CC];
    #pragma unroll
    for (int c = 0; c < CC; c++) {
      aD[c] = accD;
      aP[c] = make_float2(accP.x + bpv.x, accP.y + bpv.y);
    }
    #pragma unroll
    for (int j = 0; j < CFEAT; j++) {
      float2 wd = __ldg(Wd2 + (204+j)*32 + l);
      float2 wp = __ldg(Wp2 + (204+j)*32 + l);
      #pragma unroll
      for (int c = 0; c < CC; c++) {
        float f = myCf[c*CFEAT + j];
        aD[c].x += f*wd.x; aD[c].y += f*wd.y;
        aP[c].x += f*wp.x; aP[c].y += f*wp.y;
      }
    }
    #pragma unroll
    for (int c = 0; c < CC; c++) {
      size_t row = (size_t)c*NN + n;
      ((half2*)g_xdh)[row*32 + l] = __floats2half2_rn(aD[c].x, aD[c].y);
      ((float2*)g_xp)[row*32 + l] = aP[c];
    }
    __syncwarp();
  }
}

// ---------------- SpMM: g_y = (A+A^T) * xd (fp16 gather, fp32 accum) ----------------
__global__ void k_spmm() {
  int gw   = (blockIdx.x*blockDim.x + threadIdx.x) >> 5;
  int lane = threadIdx.x & 31;
  int nw   = (gridDim.x*blockDim.x) >> 5;
  for (int p = gw; p < ROWS; p += nw) {
    int c = p / NN;
    int n = p - c*NN;
    int beg = g_rowptr[n], end = g_rowptr[n+1];
    const half2* xs = (const half2*)g_xdh + (size_t)c*NN*32;
    float a0 = 0.f, a1 = 0.f;
    int e = beg;
    for (; e + 4 <= end; e += 4) {
      int s0 = __ldg(g_col + e);
      int s1 = __ldg(g_col + e + 1);
      int s2 = __ldg(g_col + e + 2);
      int s3 = __ldg(g_col + e + 3);
      float2 v0 = __half22float2(xs[(size_t)s0*32 + lane]);
      float2 v1 = __half22float2(xs[(size_t)s1*32 + lane]);
      float2 v2 = __half22float2(xs[(size_t)s2*32 + lane]);
      float2 v3 = __half22float2(xs[(size_t)s3*32 + lane]);
      a0 += (v0.x + v1.x) + (v2.x + v3.x);
      a1 += (v0.y + v1.y) + (v2.y + v3.y);
    }
    for (; e < end; e++) {
      int s = __ldg(g_col + e);
      float2 v = __half22float2(xs[(size_t)s*32 + lane]);
      a0 += v.x; a1 += v.y;
    }
    ((float2*)g_y)[(size_t)p*32 + lane] = make_float2(a0, a1);
  }
}

// ---------------- packed-f32x2 matvec over 8 rows ----------------
// rb2: duplicated-operand rows: rb2[r*32 + d2] = { {x[2d2],x[2d2]}, {x[2d2+1],x[2d2+1]} }
__device__ __forceinline__ void matvec2(const float* __restrict__ W,
                                        const ulonglong2* __restrict__ rb2,
                                        int lane, ull acc[GRP]) {
  const float2* W2 = (const float2*)W;
  #pragma unroll 8
  for (int d2 = 0; d2 < 32; d2++) {
    float2 wa = __ldg(W2 + (2*d2  )*32 + lane);
    float2 wb = __ldg(W2 + (2*d2+1)*32 + lane);
    ull w0 = f2_pack(wa.x, wa.y);
    ull w1 = f2_pack(wb.x, wb.y);
    #pragma unroll
    for (int r = 0; r < GRP; r++) {
      ulonglong2 b = rb2[r*32 + d2];   // LDS.128 broadcast
      fma2(acc[r], w0, b.x);
      fma2(acc[r], w1, b.y);
    }
  }
}

// combine0: x1 = l2norm(xp0 + lrelu(y + bd0)); xd1 = x1 @ Wd1
__global__ void k_combine0(const float* __restrict__ bd, const float* __restrict__ Wdn) {
  __shared__ __align__(16) ulonglong2 rbuf[8][GRP*32];
  int tid = threadIdx.x;
  int w = tid >> 5, lane = tid & 31;
  ulonglong2* rb2 = &rbuf[w][0];
  int gw = (blockIdx.x*blockDim.x + tid) >> 5;
  int nw = (gridDim.x*blockDim.x) >> 5;
  float2 bdv = __ldg((const float2*)bd + lane);
  const int NG = ROWS / GRP;
  for (int g = gw; g < NG; g += nw) {
    size_t row0 = (size_t)g * GRP;
    #pragma unroll
    for (int r = 0; r < GRP; r++) {
      size_t rw = (row0 + r)*32 + lane;
      float2 xp = ((const float2*)g_xp)[rw];
      float2 yv = ((const float2*)g_y)[rw];
      float v0 = xp.x + lrelu(yv.x + bdv.x);
      float v1 = xp.y + lrelu(yv.y + bdv.y);
      float ss = warp_sum(v0*v0 + v1*v1);
      float rn = rsqrtf(fmaxf(ss, 1e-12f));
      v0 *= rn; v1 *= rn;
      ((float2*)g_x)[rw] = make_float2(v0, v1);
      rb2[r*32 + lane] = make_ulonglong2(f2_pack(v0, v0), f2_pack(v1, v1));
    }
    __syncwarp();
    ull acc[GRP];
    #pragma unroll
    for (int r = 0; r < GRP; r++) acc[r] = 0ull;
    matvec2(Wdn, rb2, lane, acc);
    #pragma unroll
    for (int r = 0; r < GRP; r++) {
      float2 res = f2_unpack(acc[r]);
      ((half2*)g_xdh)[(row0 + r)*32 + lane] = __floats2half2_rn(res.x, res.y);
    }
    __syncwarp();
  }
}

// combine (layers 1,2): x' = l2norm(x@Wp + bp + lrelu(y + bd)); if !LAST xd = x' @ Wdn
template<bool LAST>
__global__ void k_combine(const float* __restrict__ Wp, const float* __restrict__ bp,
                          const float* __restrict__ bd, const float* __restrict__ Wdn) {
  __shared__ __align__(16) ulonglong2 rbuf[8][GRP*32];
  int tid = threadIdx.x;
  int w = tid >> 5, lane = tid & 31;
  ulonglong2* rb2 = &rbuf[w][0];
  int gw = (blockIdx.x*blockDim.x + tid) >> 5;
  int nw = (gridDim.x*blockDim.x) >> 5;
  float2 bpv = __ldg((const float2*)bp + lane);
  float2 bdv = __ldg((const float2*)bd + lane);
  ull bp2 = f2_pack(bpv.x, bpv.y);
  const int NG = ROWS / GRP;
  for (int g = gw; g < NG; g += nw) {
    size_t row0 = (size_t)g * GRP;
    #pragma unroll
    for (int r = 0; r < GRP; r++) {
      float2 xv = ((const float2*)g_x)[(row0 + r)*32 + lane];
      rb2[r*32 + lane] = make_ulonglong2(f2_pack(xv.x, xv.x), f2_pack(xv.y, xv.y));
    }
    __syncwarp();
    ull acc[GRP];
    #pragma unroll
    for (int r = 0; r < GRP; r++) acc[r] = bp2;
    matvec2(Wp, rb2, lane, acc);
    __syncwarp();
    #pragma unroll
    for (int r = 0; r < GRP; r++) {
      size_t rw = (row0 + r)*32 + lane;
      float2 a = f2_unpack(acc[r]);
      float2 yv = ((const float2*)g_y)[rw];
      float v0 = a.x + lrelu(yv.x + bdv.x);
      float v1 = a.y + lrelu(yv.y + bdv.y);
      float ss = warp_sum(v0*v0 + v1*v1);
      float rn = rsqrtf(fmaxf(ss, 1e-12f));
      v0 *= rn; v1 *= rn;
      ((float2*)g_x)[rw] = make_float2(v0, v1);
      if (!LAST)
        rb2[r*32 + lane] = make_ulonglong2(f2_pack(v0, v0), f2_pack(v1, v1));
    }
    if (!LAST) {
      __syncwarp();
      #pragma unroll
      for (int r = 0; r < GRP; r++) acc[r] = 0ull;
      matvec2(Wdn, rb2, lane, acc);
      #pragma unroll
      for (int r = 0; r < GRP; r++) {
        float2 res = f2_unpack(acc[r]);
        ((half2*)g_xdh)[(row0 + r)*32 + lane] = __floats2half2_rn(res.x, res.y);
      }
    }
    __syncwarp();
  }
}

// ---------------- pooling over sorted graph_ids ----------------
__device__ __forceinline__ int lower_bound_dev(const int* __restrict__ a, int n, int key) {
  int lo = 0, hi = n;
  while (lo < hi) { int m = (lo + hi) >> 1; if (a[m] < key) lo = m + 1; else hi = m; }
  return lo;
}

__global__ void k_pool(const int* __restrict__ gid) {
  __shared__ float red[256];
  int b = blockIdx.x / CC;
  int c = blockIdx.x - b*CC;
  int lo = lower_bound_dev(gid, NN, b);
  int hi = lower_bound_dev(gid, NN, b+1);
  int h   = threadIdx.x & 63;
  int sub = threadIdx.x >> 6;
  float acc = 0.f;
  const float* xs = g_x + (size_t)c*NN*HH;
  for (int n = lo + sub; n < hi; n += 4) acc += xs[(size_t)n*HH + h];
  red[threadIdx.x] = acc;
  __syncthreads();
  if (sub == 0)
    g_pooled[(size_t)blockIdx.x*HH + h] = red[h] + red[64+h] + red[128+h] + red[192+h];
}

// ---------------- final MLP: 64 -> 64 -> 64 -> 1 ----------------
__global__ void k_mlp(const float* __restrict__ Wm0, const float* __restrict__ bm0,
                      const float* __restrict__ Wm1, const float* __restrict__ bm1,
                      const float* __restrict__ Wm2, const float* __restrict__ bm2,
                      float* __restrict__ out) {
  __shared__ float s_in[HH], s_h[HH], rr[HH];
  int bc = blockIdx.x;
  int h = threadIdx.x;
  s_in[h] = g_pooled[(size_t)bc*HH + h];
  __syncthreads();
  float a = __ldg(bm0 + h);
  #pragma unroll 8
  for (int d = 0; d < HH; d++) a += s_in[d] * __ldg(Wm0 + d*HH + h);
  a = lrelu(a);
  s_h[h] = a;
  __syncthreads();
  float a2 = __ldg(bm1 + h);
  #pragma unroll 8
  for (int d = 0; d < HH; d++) a2 += s_h[d] * __ldg(Wm1 + d*HH + h);
  a2 = lrelu(a2);
  rr[h] = a2 * __ldg(Wm2 + h);
  __syncthreads();
  if (h < 32) {
    float v = rr[h] + rr[h+32];
    v = warp_sum(v);
    if (h == 0) out[bc] = v + __ldg(bm2);
  }
}

// ---------------- host orchestration ----------------
extern "C" void kernel_launch(void* const* d_in, const int* in_sizes, int n_in,
                              void* d_out, int out_size) {
  (void)in_sizes; (void)n_in; (void)out_size;
  const float* node_feats   = (const float*)d_in[0];
  const float* config_feats = (const float*)d_in[1];
  const int*   op_ids       = (const int*)  d_in[2];
  const int*   src          = (const int*)  d_in[3];
  const int*   dst          = (const int*)  d_in[4];
  const int*   graph_ids    = (const int*)  d_in[5];
  const float* op_emb       = (const float*)d_in[6];
  const float* W_d0 = (const float*)d_in[7];  const float* b_d0 = (const float*)d_in[8];
  const float* W_p0 = (const float*)d_in[9];  const float* b_p0 = (const float*)d_in[10];
  const float* W_d1 = (const float*)d_in[11]; const float* b_d1 = (const float*)d_in[12];
  const float* W_p1 = (const float*)d_in[13]; const float* b_p1 = (const float*)d_in[14];
  const float* W_d2 = (const float*)d_in[15]; const float* b_d2 = (const float*)d_in[16];
  const float* W_p2 = (const float*)d_in[17]; const float* b_p2 = (const float*)d_in[18];
  const float* W_m0 = (const float*)d_in[19]; const float* b_m0 = (const float*)d_in[20];
  const float* W_m1 = (const float*)d_in[21]; const float* b_m1 = (const float*)d_in[22];
  const float* W_m2 = (const float*)d_in[23]; const float* b_m2 = (const float*)d_in[24];
  float* out = (float*)d_out;

  // CSR build
  k_zero_counts<<<(NN+255)/256, 256>>>();
  k_count<<<(EE/4+255)/256, 256>>>(src, dst);
  k_scan<<<1, 1024>>>();
  k_fill<<<(EE+255)/256, 256>>>(src, dst);

  // layer 0
  k_layer0<<<2048, 256>>>(node_feats, config_feats, op_ids, op_emb, W_d0, W_p0, b_p0);
  k_spmm<<<2048, 256>>>();
  k_combine0<<<2048, 256>>>(b_d0, W_d1);

  // layer 1
  k_spmm<<<2048, 256>>>();
  k_combine<false><<<2048, 256>>>(W_p1, b_p1, b_d1, W_d2);

  // layer 2
  k_spmm<<<2048, 256>>>();
  k_combine<true><<<2048, 256>>>(W_p2, b_p2, b_d2, (const float*)nullptr);

  // pooling + MLP head
  k_pool<<<BB*CC, 256>>>(graph_ids);
  k_mlp<<<BB*CC, HH>>>(W_m0, b_m0, W_m1, b_m1, W_m2, b_m2, out);
}